// round 2
// baseline (speedup 1.0000x reference)
#include <cuda_runtime.h>
#include <cuda_bf16.h>
#include <math.h>

// Problem constants
#define T 256
#define HD 1024
#define ID 768
#define NE 32
#define TK 6
#define NG 8
#define GSZ 4   // experts per group (32/8)
#define KG 4    // top-k groups

// ---------------- scratch (device globals; no allocation allowed) ----------------
__device__ int   g_cnt[NE];
__device__ int   g_tok[NE * T];
__device__ int   g_slot[NE * T];
__device__ float g_wt[T * TK];
__device__ float g_act[(size_t)NE * T * ID];   // [e][j][i]  ~24 MB
__device__ float g_y[(size_t)T * TK * HD];     // [t][k][h]  ~6 MB

// ---------------- kernel 1: routing ----------------
// Single block, 256 threads, one thread per token.
__global__ void routing_kernel(const float* __restrict__ logits,
                               const float* __restrict__ bias) {
    int tid = threadIdx.x;
    if (tid < NE) g_cnt[tid] = 0;
    __syncthreads();

    int t = tid;
    float s[NE], sc[NE];
#pragma unroll
    for (int e = 0; e < NE; e++) {
        float l = logits[t * NE + e];
        float sig = 1.0f / (1.0f + expf(-l));
        s[e] = sig;
        sc[e] = sig + bias[e];
    }
    // group scores = sum of top-2 within each group of 4
    float gs[NG];
#pragma unroll
    for (int g = 0; g < NG; g++) {
        float m1 = -3.4e38f, m2 = -3.4e38f;
#pragma unroll
        for (int j = 0; j < GSZ; j++) {
            float v = sc[g * GSZ + j];
            if (v > m1) { m2 = m1; m1 = v; }
            else if (v > m2) { m2 = v; }
        }
        gs[g] = m1 + m2;
    }
    // top-4 groups (strict > keeps lowest index on ties, matching lax.top_k)
    bool gsel[NG];
#pragma unroll
    for (int g = 0; g < NG; g++) gsel[g] = false;
#pragma unroll
    for (int it = 0; it < KG; it++) {
        float best = -3.4e38f; int bi = 0;
#pragma unroll
        for (int g = 0; g < NG; g++)
            if (!gsel[g] && gs[g] > best) { best = gs[g]; bi = g; }
        gsel[bi] = true;
    }
    // masked top-6 experts by corrected score
    float msc[NE];
#pragma unroll
    for (int e = 0; e < NE; e++)
        msc[e] = gsel[e / GSZ] ? sc[e] : -3.4e38f;

    int ids[TK];
    float w[TK];
    float wsum = 0.0f;
#pragma unroll
    for (int k = 0; k < TK; k++) {
        float best = -3.4e38f; int bi = 0;
#pragma unroll
        for (int e = 0; e < NE; e++)
            if (msc[e] > best) { best = msc[e]; bi = e; }
        ids[k] = bi;
        msc[bi] = -3.4e38f;
        w[k] = s[bi];               // weights from UNBIASED scores
        wsum += w[k];
    }
    float inv = 1.0f / wsum;
#pragma unroll
    for (int k = 0; k < TK; k++) {
        g_wt[t * TK + k] = w[k] * inv;
        int e = ids[k];
        int j = atomicAdd(&g_cnt[e], 1);
        g_tok[e * T + j]  = t;
        g_slot[e * T + j] = k;
    }
}

// ---------------- kernel 2: grouped GEMM1 + SiLU ----------------
// act[e][m][i] = silu(h[m]·w13_gate[e][i]) * (h[m]·w13_up[e][i])
// tile: 64(m) x 64(i), K=1024 in 16-chunks; 256 threads, 4x4 microtile, dual acc.
// smem tiles padded by +4 floats so rows stay 16B-aligned -> LDS.128 operand fetch.
#define BM 64
#define BN 64
#define BK 16
#define PAD 4

__global__ void gemm1_kernel(const float* __restrict__ hidden,
                             const float* __restrict__ w13) {
    int e = blockIdx.z;
    int cnt = g_cnt[e];
    int m0 = blockIdx.y * BM;
    if (m0 >= cnt) return;
    int i0 = blockIdx.x * BN;

    __shared__ float As[BK][BM + PAD];
    __shared__ float Bg[BK][BN + PAD];
    __shared__ float Bu[BK][BN + PAD];
    __shared__ int toks[BM];

    int tid = threadIdx.x;
    if (tid < BM) {
        int m = m0 + tid;
        toks[tid] = (m < cnt) ? g_tok[e * T + m] : -1;
    }
    __syncthreads();

    int tx = tid & 15;       // n-group
    int ty = tid >> 4;       // m-group
    int lm = tid >> 2;       // 0..63 load row
    int lk = (tid & 3) * 4;  // 0,4,8,12

    const float* w13e = w13 + (size_t)e * 2 * ID * HD;

    float accg[4][4] = {{0}}, accu[4][4] = {{0}};

    for (int k0 = 0; k0 < HD; k0 += BK) {
        // A (gathered token rows)
        float4 av = make_float4(0.f, 0.f, 0.f, 0.f);
        int tok = toks[lm];
        if (tok >= 0)
            av = *(const float4*)(hidden + (size_t)tok * HD + k0 + lk);
        As[lk + 0][lm] = av.x; As[lk + 1][lm] = av.y;
        As[lk + 2][lm] = av.z; As[lk + 3][lm] = av.w;
        // B gate rows [i0+lm], up rows [768+i0+lm]
        float4 bv = *(const float4*)(w13e + (size_t)(i0 + lm) * HD + k0 + lk);
        Bg[lk + 0][lm] = bv.x; Bg[lk + 1][lm] = bv.y;
        Bg[lk + 2][lm] = bv.z; Bg[lk + 3][lm] = bv.w;
        float4 cv = *(const float4*)(w13e + (size_t)(ID + i0 + lm) * HD + k0 + lk);
        Bu[lk + 0][lm] = cv.x; Bu[lk + 1][lm] = cv.y;
        Bu[lk + 2][lm] = cv.z; Bu[lk + 3][lm] = cv.w;
        __syncthreads();

#pragma unroll
        for (int kk = 0; kk < BK; kk++) {
            float4 a  = *(const float4*)&As[kk][ty * 4];
            float4 bg = *(const float4*)&Bg[kk][tx * 4];
            float4 bu = *(const float4*)&Bu[kk][tx * 4];
            float am[4] = {a.x, a.y, a.z, a.w};
            float bgv[4] = {bg.x, bg.y, bg.z, bg.w};
            float buv[4] = {bu.x, bu.y, bu.z, bu.w};
#pragma unroll
            for (int mi = 0; mi < 4; mi++)
#pragma unroll
                for (int ni = 0; ni < 4; ni++) {
                    accg[mi][ni] += am[mi] * bgv[ni];
                    accu[mi][ni] += am[mi] * buv[ni];
                }
        }
        __syncthreads();
    }

#pragma unroll
    for (int mi = 0; mi < 4; mi++) {
        int m = m0 + ty * 4 + mi;
        if (m >= cnt) continue;
        float* actp = g_act + ((size_t)(e * T + m)) * ID + i0 + tx * 4;
#pragma unroll
        for (int ni = 0; ni < 4; ni++) {
            float g = accg[mi][ni];
            float u = accu[mi][ni];
            float sig = 1.0f / (1.0f + expf(-g));
            actp[ni] = g * sig * u;
        }
    }
}

// ---------------- kernel 3: grouped GEMM2 ----------------
// y[t][slot][h] = act[e][m]·w2[e][h][:]
__global__ void gemm2_kernel(const float* __restrict__ w2) {
    int e = blockIdx.z;
    int cnt = g_cnt[e];
    int m0 = blockIdx.y * BM;
    if (m0 >= cnt) return;
    int h0 = blockIdx.x * BN;

    __shared__ float As[BK][BM + PAD];
    __shared__ float Bs[BK][BN + PAD];

    int tid = threadIdx.x;
    int tx = tid & 15;
    int ty = tid >> 4;
    int lm = tid >> 2;
    int lk = (tid & 3) * 4;

    const float* w2e = w2 + (size_t)e * HD * ID;
    const float* acte = g_act + (size_t)e * T * ID;

    float acc[4][4] = {{0}};

    for (int k0 = 0; k0 < ID; k0 += BK) {
        float4 av = make_float4(0.f, 0.f, 0.f, 0.f);
        if (m0 + lm < cnt)
            av = *(const float4*)(acte + (size_t)(m0 + lm) * ID + k0 + lk);
        As[lk + 0][lm] = av.x; As[lk + 1][lm] = av.y;
        As[lk + 2][lm] = av.z; As[lk + 3][lm] = av.w;

        float4 bv = *(const float4*)(w2e + (size_t)(h0 + lm) * ID + k0 + lk);
        Bs[lk + 0][lm] = bv.x; Bs[lk + 1][lm] = bv.y;
        Bs[lk + 2][lm] = bv.z; Bs[lk + 3][lm] = bv.w;
        __syncthreads();

#pragma unroll
        for (int kk = 0; kk < BK; kk++) {
            float4 a = *(const float4*)&As[kk][ty * 4];
            float4 b = *(const float4*)&Bs[kk][tx * 4];
            float am[4] = {a.x, a.y, a.z, a.w};
            float bv4[4] = {b.x, b.y, b.z, b.w};
#pragma unroll
            for (int mi = 0; mi < 4; mi++)
#pragma unroll
                for (int ni = 0; ni < 4; ni++)
                    acc[mi][ni] += am[mi] * bv4[ni];
        }
        __syncthreads();
    }

#pragma unroll
    for (int mi = 0; mi < 4; mi++) {
        int m = m0 + ty * 4 + mi;
        if (m >= cnt) continue;
        int t = g_tok[e * T + m];
        int s = g_slot[e * T + m];
        float* yp = g_y + ((size_t)(t * TK + s)) * HD + h0 + tx * 4;
#pragma unroll
        for (int ni = 0; ni < 4; ni++) yp[ni] = acc[mi][ni];
    }
}

// ---------------- kernel 4: weighted combine ----------------
__global__ void combine_kernel(float* __restrict__ out) {
    int idx = blockIdx.x * blockDim.x + threadIdx.x;   // over T*HD/4
    int t = idx / (HD / 4);
    int h4 = (idx % (HD / 4)) * 4;
    float4 o = make_float4(0.f, 0.f, 0.f, 0.f);
#pragma unroll
    for (int k = 0; k < TK; k++) {
        float w = g_wt[t * TK + k];
        float4 yv = *(const float4*)(g_y + ((size_t)(t * TK + k)) * HD + h4);
        o.x += w * yv.x; o.y += w * yv.y; o.z += w * yv.z; o.w += w * yv.w;
    }
    *(float4*)(out + (size_t)t * HD + h4) = o;
}

// ---------------- launcher ----------------
extern "C" void kernel_launch(void* const* d_in, const int* in_sizes, int n_in,
                              void* d_out, int out_size) {
    const float* hidden = (const float*)d_in[0];
    const float* logits = (const float*)d_in[1];
    const float* bias   = (const float*)d_in[2];
    const float* w13    = (const float*)d_in[3];
    const float* w2     = (const float*)d_in[4];
    float* out = (float*)d_out;

    routing_kernel<<<1, 256>>>(logits, bias);

    dim3 g1(ID / BN, T / BM, NE);   // 12 x 4 x 32
    gemm1_kernel<<<g1, 256>>>(hidden, w13);

    dim3 g2(HD / BN, T / BM, NE);   // 16 x 4 x 32
    gemm2_kernel<<<g2, 256>>>(w2);

    combine_kernel<<<(T * HD / 4) / 256, 256>>>(out);
}

// round 5
// speedup vs baseline: 1.5024x; 1.5024x over previous
#include <cuda_runtime.h>
#include <cuda_bf16.h>
#include <math.h>

// Problem constants
#define T 256
#define HD 1024
#define ID 768
#define NE 32
#define TK 6
#define NG 8
#define GSZ 4   // experts per group
#define KG 4    // top-k groups

#define BM 64
#define BK 32
#define LSTR (BK + 4)   // 36 floats: fragment LDS conflict-free, float4-aligned rows

// ---------------- scratch ----------------
__device__ int   g_cnt[NE];
__device__ int   g_tok[NE * T];
__device__ int   g_slot[NE * T];
__device__ float g_wt[T * TK];
__device__ float g_act[(size_t)NE * T * ID];   // [e][m][i]
__device__ float g_y[(size_t)T * TK * HD];     // [t][k][h]

// ---------------- routing ----------------
__global__ void routing_kernel(const float* __restrict__ logits,
                               const float* __restrict__ bias) {
    int tid = threadIdx.x;
    if (tid < NE) g_cnt[tid] = 0;
    __syncthreads();

    int t = tid;
    float s[NE], sc[NE];
#pragma unroll
    for (int e = 0; e < NE; e++) {
        float l = logits[t * NE + e];
        float sig = 1.0f / (1.0f + expf(-l));
        s[e] = sig;
        sc[e] = sig + bias[e];
    }
    float gs[NG];
#pragma unroll
    for (int g = 0; g < NG; g++) {
        float m1 = -3.4e38f, m2 = -3.4e38f;
#pragma unroll
        for (int j = 0; j < GSZ; j++) {
            float v = sc[g * GSZ + j];
            if (v > m1) { m2 = m1; m1 = v; }
            else if (v > m2) { m2 = v; }
        }
        gs[g] = m1 + m2;
    }
    bool gsel[NG];
#pragma unroll
    for (int g = 0; g < NG; g++) gsel[g] = false;
#pragma unroll
    for (int it = 0; it < KG; it++) {
        float best = -3.4e38f; int bi = 0;
#pragma unroll
        for (int g = 0; g < NG; g++)
            if (!gsel[g] && gs[g] > best) { best = gs[g]; bi = g; }
        gsel[bi] = true;
    }
    float msc[NE];
#pragma unroll
    for (int e = 0; e < NE; e++)
        msc[e] = gsel[e / GSZ] ? sc[e] : -3.4e38f;

    int ids[TK]; float w[TK]; float wsum = 0.0f;
#pragma unroll
    for (int k = 0; k < TK; k++) {
        float best = -3.4e38f; int bi = 0;
#pragma unroll
        for (int e = 0; e < NE; e++)
            if (msc[e] > best) { best = msc[e]; bi = e; }
        ids[k] = bi;
        msc[bi] = -3.4e38f;
        w[k] = s[bi];
        wsum += w[k];
    }
    float inv = 1.0f / wsum;
#pragma unroll
    for (int k = 0; k < TK; k++) {
        g_wt[t * TK + k] = w[k] * inv;
        int e = ids[k];
        int j = atomicAdd(&g_cnt[e], 1);
        g_tok[e * T + j]  = t;
        g_slot[e * T + j] = k;
    }
}

// ---------------- tf32 mma helpers ----------------
__device__ __forceinline__ void mma8(float* c, const unsigned* a, const unsigned* b) {
    asm volatile(
        "mma.sync.aligned.m16n8k8.row.col.f32.tf32.tf32.f32 "
        "{%0,%1,%2,%3}, {%4,%5,%6,%7}, {%8,%9}, {%0,%1,%2,%3};\n"
        : "+f"(c[0]), "+f"(c[1]), "+f"(c[2]), "+f"(c[3])
        : "r"(a[0]), "r"(a[1]), "r"(a[2]), "r"(a[3]), "r"(b[0]), "r"(b[1]));
}
// 3xTF32 split: hi = top 19 bits (exactly representable in tf32), lo = residual
__device__ __forceinline__ void split2(float v, unsigned& hi, unsigned& lo) {
    unsigned h = __float_as_uint(v) & 0xFFFFE000u;
    hi = h;
    lo = __float_as_uint(v - __uint_as_float(h));
}

// ---------------- GEMM1 + SiLU (tensor core, 3xTF32) ----------------
// act[e][m][i] = silu(h[m]·w13g[i]) * (h[m]·w13u[i])
// block: 64(m) x 64(i), 8 warps (4m x 2n), each warp m16 x n32 (gate & up)
__global__ __launch_bounds__(256) void gemm1_kernel(const float* __restrict__ hidden,
                                                    const float* __restrict__ w13) {
    int e = blockIdx.z;
    int cnt = g_cnt[e];
    int m0 = blockIdx.y * BM;
    if (m0 >= cnt) return;
    int i0 = blockIdx.x * 64;

    __shared__ float As[BM][LSTR];
    __shared__ float Bg[64][LSTR];
    __shared__ float Bu[64][LSTR];
    __shared__ int toks[BM];

    int tid = threadIdx.x;
    int lane = tid & 31, wid = tid >> 5;
    int wm = wid & 3, wn = wid >> 2;
    int gid = lane >> 2, tg = lane & 3;

    if (tid < BM) toks[tid] = (m0 + tid < cnt) ? g_tok[e * T + m0 + tid] : -1;
    __syncthreads();

    const float* w13e = w13 + (size_t)e * 2 * ID * HD;

    float cg[4][4], cu[4][4];
#pragma unroll
    for (int j = 0; j < 4; j++)
#pragma unroll
        for (int q = 0; q < 4; q++) { cg[j][q] = 0.f; cu[j][q] = 0.f; }

    int lr = tid >> 3;        // 0..31 (2 row passes)
    int lc = (tid & 7) * 4;   // 0..28

    for (int k0 = 0; k0 < HD; k0 += BK) {
#pragma unroll
        for (int rr = 0; rr < 2; rr++) {
            int row = lr + rr * 32;
            int tok = toks[row];
            float4 v = (tok >= 0)
                ? *(const float4*)(hidden + (size_t)tok * HD + k0 + lc)
                : make_float4(0.f, 0.f, 0.f, 0.f);
            *(float4*)&As[row][lc] = v;
            *(float4*)&Bg[row][lc] = *(const float4*)(w13e + (size_t)(i0 + row) * HD + k0 + lc);
            *(float4*)&Bu[row][lc] = *(const float4*)(w13e + (size_t)(ID + i0 + row) * HD + k0 + lc);
        }
        __syncthreads();

#pragma unroll
        for (int kk = 0; kk < BK; kk += 8) {
            unsigned ah[4], al[4];
            int mrow = wm * 16 + gid;
            split2(As[mrow][kk + tg],         ah[0], al[0]);
            split2(As[mrow + 8][kk + tg],     ah[1], al[1]);
            split2(As[mrow][kk + tg + 4],     ah[2], al[2]);
            split2(As[mrow + 8][kk + tg + 4], ah[3], al[3]);
#pragma unroll
            for (int j = 0; j < 4; j++) {
                int nrow = wn * 32 + j * 8 + gid;
                unsigned bh[2], bl[2];
                split2(Bg[nrow][kk + tg],     bh[0], bl[0]);
                split2(Bg[nrow][kk + tg + 4], bh[1], bl[1]);
                mma8(cg[j], al, bh); mma8(cg[j], ah, bl); mma8(cg[j], ah, bh);
                split2(Bu[nrow][kk + tg],     bh[0], bl[0]);
                split2(Bu[nrow][kk + tg + 4], bh[1], bl[1]);
                mma8(cu[j], al, bh); mma8(cu[j], ah, bl); mma8(cu[j], ah, bh);
            }
        }
        __syncthreads();
    }

#pragma unroll
    for (int j = 0; j < 4; j++) {
        int col = i0 + wn * 32 + j * 8 + tg * 2;
#pragma unroll
        for (int half = 0; half < 2; half++) {
            int m = m0 + wm * 16 + gid + half * 8;
            if (m < cnt) {
                float g0 = cg[j][half * 2], g1 = cg[j][half * 2 + 1];
                float u0 = cu[j][half * 2], u1 = cu[j][half * 2 + 1];
                float a0 = g0 / (1.f + expf(-g0)) * u0;
                float a1 = g1 / (1.f + expf(-g1)) * u1;
                *(float2*)(g_act + ((size_t)(e * T + m)) * ID + col) = make_float2(a0, a1);
            }
        }
    }
}

// ---------------- GEMM2 (tensor core, 3xTF32) ----------------
// y[t][slot][h] = act[e][m]·w2[e][h]
__global__ __launch_bounds__(256) void gemm2_kernel(const float* __restrict__ w2) {
    int e = blockIdx.z;
    int cnt = g_cnt[e];
    int m0 = blockIdx.y * BM;
    if (m0 >= cnt) return;
    int h0 = blockIdx.x * 64;

    __shared__ float As[BM][LSTR];
    __shared__ float Bs[64][LSTR];

    int tid = threadIdx.x;
    int lane = tid & 31, wid = tid >> 5;
    int wm = wid & 3, wn = wid >> 2;
    int gid = lane >> 2, tg = lane & 3;

    const float* w2e = w2 + (size_t)e * HD * ID;
    const float* acte = g_act + (size_t)e * T * ID;

    float acc[4][4];
#pragma unroll
    for (int j = 0; j < 4; j++)
#pragma unroll
        for (int q = 0; q < 4; q++) acc[j][q] = 0.f;

    int lr = tid >> 3;
    int lc = (tid & 7) * 4;

    for (int k0 = 0; k0 < ID; k0 += BK) {
#pragma unroll
        for (int rr = 0; rr < 2; rr++) {
            int row = lr + rr * 32;
            float4 v = (m0 + row < cnt)
                ? *(const float4*)(acte + (size_t)(m0 + row) * ID + k0 + lc)
                : make_float4(0.f, 0.f, 0.f, 0.f);
            *(float4*)&As[row][lc] = v;
            *(float4*)&Bs[row][lc] = *(const float4*)(w2e + (size_t)(h0 + row) * ID + k0 + lc);
        }
        __syncthreads();

#pragma unroll
        for (int kk = 0; kk < BK; kk += 8) {
            unsigned ah[4], al[4];
            int mrow = wm * 16 + gid;
            split2(As[mrow][kk + tg],         ah[0], al[0]);
            split2(As[mrow + 8][kk + tg],     ah[1], al[1]);
            split2(As[mrow][kk + tg + 4],     ah[2], al[2]);
            split2(As[mrow + 8][kk + tg + 4], ah[3], al[3]);
#pragma unroll
            for (int j = 0; j < 4; j++) {
                int nrow = wn * 32 + j * 8 + gid;
                unsigned bh[2], bl[2];
                split2(Bs[nrow][kk + tg],     bh[0], bl[0]);
                split2(Bs[nrow][kk + tg + 4], bh[1], bl[1]);
                mma8(acc[j], al, bh); mma8(acc[j], ah, bl); mma8(acc[j], ah, bh);
            }
        }
        __syncthreads();
    }

    // epilogue: per-row token/slot lookup, store to y
    int mA = m0 + wm * 16 + gid;
    int mB = mA + 8;
    int tA = 0, sA = 0, tB = 0, sB = 0;
    if (mA < cnt) { tA = g_tok[e * T + mA]; sA = g_slot[e * T + mA]; }
    if (mB < cnt) { tB = g_tok[e * T + mB]; sB = g_slot[e * T + mB]; }
#pragma unroll
    for (int j = 0; j < 4; j++) {
        int col = h0 + wn * 32 + j * 8 + tg * 2;
        if (mA < cnt)
            *(float2*)(g_y + ((size_t)(tA * TK + sA)) * HD + col)
                = make_float2(acc[j][0], acc[j][1]);
        if (mB < cnt)
            *(float2*)(g_y + ((size_t)(tB * TK + sB)) * HD + col)
                = make_float2(acc[j][2], acc[j][3]);
    }
}

// ---------------- combine ----------------
__global__ void combine_kernel(float* __restrict__ out) {
    int idx = blockIdx.x * blockDim.x + threadIdx.x;
    int t = idx / (HD / 4);
    int h4 = (idx % (HD / 4)) * 4;
    float4 o = make_float4(0.f, 0.f, 0.f, 0.f);
#pragma unroll
    for (int k = 0; k < TK; k++) {
        float w = g_wt[t * TK + k];
        float4 yv = *(const float4*)(g_y + ((size_t)(t * TK + k)) * HD + h4);
        o.x += w * yv.x; o.y += w * yv.y; o.z += w * yv.z; o.w += w * yv.w;
    }
    *(float4*)(out + (size_t)t * HD + h4) = o;
}

// ---------------- launcher ----------------
extern "C" void kernel_launch(void* const* d_in, const int* in_sizes, int n_in,
                              void* d_out, int out_size) {
    const float* hidden = (const float*)d_in[0];
    const float* logits = (const float*)d_in[1];
    const float* bias   = (const float*)d_in[2];
    const float* w13    = (const float*)d_in[3];
    const float* w2     = (const float*)d_in[4];
    float* out = (float*)d_out;

    routing_kernel<<<1, 256>>>(logits, bias);

    dim3 g1(ID / 64, T / BM, NE);   // 12 x 4 x 32
    gemm1_kernel<<<g1, 256>>>(hidden, w13);

    dim3 g2(HD / 64, T / BM, NE);   // 16 x 4 x 32
    gemm2_kernel<<<g2, 256>>>(w2);

    combine_kernel<<<(T * HD / 4) / 256, 256>>>(out);
}

// round 6
// speedup vs baseline: 1.5195x; 1.0114x over previous
#include <cuda_runtime.h>
#include <cuda_bf16.h>
#include <math.h>

// Problem constants
#define T 256
#define HD 1024
#define ID 768
#define NE 32
#define TK 6
#define NG 8
#define GSZ 4   // experts per group
#define KG 4    // top-k groups

#define BM 64
#define BK 32
#define LSTR (BK + 4)   // 36 floats: fragment LDS conflict-free, float4-aligned rows

// ---------------- scratch ----------------
__device__ int   g_cnt[NE];
__device__ int   g_tok[NE * T];
__device__ int   g_slot[NE * T];
__device__ float g_wt[T * TK];
__device__ float g_act[(size_t)NE * T * ID];   // [e][m][i]
__device__ float g_y[(size_t)T * TK * HD];     // [t][k][h]

// ---------------- routing ----------------
__global__ void routing_kernel(const float* __restrict__ logits,
                               const float* __restrict__ bias) {
    int tid = threadIdx.x;
    if (tid < NE) g_cnt[tid] = 0;
    __syncthreads();

    int t = tid;
    float s[NE], sc[NE];
#pragma unroll
    for (int e = 0; e < NE; e++) {
        float l = logits[t * NE + e];
        float sig = 1.0f / (1.0f + expf(-l));
        s[e] = sig;
        sc[e] = sig + bias[e];
    }
    float gs[NG];
#pragma unroll
    for (int g = 0; g < NG; g++) {
        float m1 = -3.4e38f, m2 = -3.4e38f;
#pragma unroll
        for (int j = 0; j < GSZ; j++) {
            float v = sc[g * GSZ + j];
            if (v > m1) { m2 = m1; m1 = v; }
            else if (v > m2) { m2 = v; }
        }
        gs[g] = m1 + m2;
    }
    bool gsel[NG];
#pragma unroll
    for (int g = 0; g < NG; g++) gsel[g] = false;
#pragma unroll
    for (int it = 0; it < KG; it++) {
        float best = -3.4e38f; int bi = 0;
#pragma unroll
        for (int g = 0; g < NG; g++)
            if (!gsel[g] && gs[g] > best) { best = gs[g]; bi = g; }
        gsel[bi] = true;
    }
    float msc[NE];
#pragma unroll
    for (int e = 0; e < NE; e++)
        msc[e] = gsel[e / GSZ] ? sc[e] : -3.4e38f;

    int ids[TK]; float w[TK]; float wsum = 0.0f;
#pragma unroll
    for (int k = 0; k < TK; k++) {
        float best = -3.4e38f; int bi = 0;
#pragma unroll
        for (int e = 0; e < NE; e++)
            if (msc[e] > best) { best = msc[e]; bi = e; }
        ids[k] = bi;
        msc[bi] = -3.4e38f;
        w[k] = s[bi];
        wsum += w[k];
    }
    float inv = 1.0f / wsum;
#pragma unroll
    for (int k = 0; k < TK; k++) {
        g_wt[t * TK + k] = w[k] * inv;
        int e = ids[k];
        int j = atomicAdd(&g_cnt[e], 1);
        g_tok[e * T + j]  = t;
        g_slot[e * T + j] = k;
    }
}

// ---------------- tf32 mma helpers ----------------
__device__ __forceinline__ void mma8(float* c, const unsigned* a, const unsigned* b) {
    asm volatile(
        "mma.sync.aligned.m16n8k8.row.col.f32.tf32.tf32.f32 "
        "{%0,%1,%2,%3}, {%4,%5,%6,%7}, {%8,%9}, {%0,%1,%2,%3};\n"
        : "+f"(c[0]), "+f"(c[1]), "+f"(c[2]), "+f"(c[3])
        : "r"(a[0]), "r"(a[1]), "r"(a[2]), "r"(a[3]), "r"(b[0]), "r"(b[1]));
}
// 3xTF32 split: hi = top 19 bits (exactly representable in tf32), lo = residual
__device__ __forceinline__ void split2(float v, unsigned& hi, unsigned& lo) {
    unsigned h = __float_as_uint(v) & 0xFFFFE000u;
    hi = h;
    lo = __float_as_uint(v - __uint_as_float(h));
}

// ---------------- GEMM1 + SiLU (tensor core, 3xTF32) ----------------
// act[e][m][i] = silu(h[m]·w13g[i]) * (h[m]·w13u[i])
// block: 64(m) x 64(i), 8 warps (4m x 2n), each warp m16 x n32 (gate & up)
__global__ __launch_bounds__(256) void gemm1_kernel(const float* __restrict__ hidden,
                                                    const float* __restrict__ w13) {
    int e = blockIdx.z;
    int cnt = g_cnt[e];
    int m0 = blockIdx.y * BM;
    if (m0 >= cnt) return;
    int i0 = blockIdx.x * 64;

    __shared__ float As[BM][LSTR];
    __shared__ float Bg[64][LSTR];
    __shared__ float Bu[64][LSTR];
    __shared__ int toks[BM];

    int tid = threadIdx.x;
    int lane = tid & 31, wid = tid >> 5;
    int wm = wid & 3, wn = wid >> 2;
    int gid = lane >> 2, tg = lane & 3;

    if (tid < BM) toks[tid] = (m0 + tid < cnt) ? g_tok[e * T + m0 + tid] : -1;
    __syncthreads();

    const float* w13e = w13 + (size_t)e * 2 * ID * HD;

    float cg[4][4], cu[4][4];
#pragma unroll
    for (int j = 0; j < 4; j++)
#pragma unroll
        for (int q = 0; q < 4; q++) { cg[j][q] = 0.f; cu[j][q] = 0.f; }

    int lr = tid >> 3;        // 0..31 (2 row passes)
    int lc = (tid & 7) * 4;   // 0..28

    for (int k0 = 0; k0 < HD; k0 += BK) {
#pragma unroll
        for (int rr = 0; rr < 2; rr++) {
            int row = lr + rr * 32;
            int tok = toks[row];
            float4 v = (tok >= 0)
                ? *(const float4*)(hidden + (size_t)tok * HD + k0 + lc)
                : make_float4(0.f, 0.f, 0.f, 0.f);
            *(float4*)&As[row][lc] = v;
            *(float4*)&Bg[row][lc] = *(const float4*)(w13e + (size_t)(i0 + row) * HD + k0 + lc);
            *(float4*)&Bu[row][lc] = *(const float4*)(w13e + (size_t)(ID + i0 + row) * HD + k0 + lc);
        }
        __syncthreads();

#pragma unroll
        for (int kk = 0; kk < BK; kk += 8) {
            unsigned ah[4], al[4];
            int mrow = wm * 16 + gid;
            split2(As[mrow][kk + tg],         ah[0], al[0]);
            split2(As[mrow + 8][kk + tg],     ah[1], al[1]);
            split2(As[mrow][kk + tg + 4],     ah[2], al[2]);
            split2(As[mrow + 8][kk + tg + 4], ah[3], al[3]);
#pragma unroll
            for (int j = 0; j < 4; j++) {
                int nrow = wn * 32 + j * 8 + gid;
                unsigned bh[2], bl[2];
                split2(Bg[nrow][kk + tg],     bh[0], bl[0]);
                split2(Bg[nrow][kk + tg + 4], bh[1], bl[1]);
                mma8(cg[j], al, bh); mma8(cg[j], ah, bl); mma8(cg[j], ah, bh);
                split2(Bu[nrow][kk + tg],     bh[0], bl[0]);
                split2(Bu[nrow][kk + tg + 4], bh[1], bl[1]);
                mma8(cu[j], al, bh); mma8(cu[j], ah, bl); mma8(cu[j], ah, bh);
            }
        }
        __syncthreads();
    }

#pragma unroll
    for (int j = 0; j < 4; j++) {
        int col = i0 + wn * 32 + j * 8 + tg * 2;
#pragma unroll
        for (int half = 0; half < 2; half++) {
            int m = m0 + wm * 16 + gid + half * 8;
            if (m < cnt) {
                float g0 = cg[j][half * 2], g1 = cg[j][half * 2 + 1];
                float u0 = cu[j][half * 2], u1 = cu[j][half * 2 + 1];
                float a0 = g0 / (1.f + expf(-g0)) * u0;
                float a1 = g1 / (1.f + expf(-g1)) * u1;
                *(float2*)(g_act + ((size_t)(e * T + m)) * ID + col) = make_float2(a0, a1);
            }
        }
    }
}

// ---------------- GEMM2 (tensor core, 3xTF32) ----------------
// y[t][slot][h] = act[e][m]·w2[e][h]
__global__ __launch_bounds__(256) void gemm2_kernel(const float* __restrict__ w2) {
    int e = blockIdx.z;
    int cnt = g_cnt[e];
    int m0 = blockIdx.y * BM;
    if (m0 >= cnt) return;
    int h0 = blockIdx.x * 64;

    __shared__ float As[BM][LSTR];
    __shared__ float Bs[64][LSTR];

    int tid = threadIdx.x;
    int lane = tid & 31, wid = tid >> 5;
    int wm = wid & 3, wn = wid >> 2;
    int gid = lane >> 2, tg = lane & 3;

    const float* w2e = w2 + (size_t)e * HD * ID;
    const float* acte = g_act + (size_t)e * T * ID;

    float acc[4][4];
#pragma unroll
    for (int j = 0; j < 4; j++)
#pragma unroll
        for (int q = 0; q < 4; q++) acc[j][q] = 0.f;

    int lr = tid >> 3;
    int lc = (tid & 7) * 4;

    for (int k0 = 0; k0 < ID; k0 += BK) {
#pragma unroll
        for (int rr = 0; rr < 2; rr++) {
            int row = lr + rr * 32;
            float4 v = (m0 + row < cnt)
                ? *(const float4*)(acte + (size_t)(m0 + row) * ID + k0 + lc)
                : make_float4(0.f, 0.f, 0.f, 0.f);
            *(float4*)&As[row][lc] = v;
            *(float4*)&Bs[row][lc] = *(const float4*)(w2e + (size_t)(h0 + row) * ID + k0 + lc);
        }
        __syncthreads();

#pragma unroll
        for (int kk = 0; kk < BK; kk += 8) {
            unsigned ah[4], al[4];
            int mrow = wm * 16 + gid;
            split2(As[mrow][kk + tg],         ah[0], al[0]);
            split2(As[mrow + 8][kk + tg],     ah[1], al[1]);
            split2(As[mrow][kk + tg + 4],     ah[2], al[2]);
            split2(As[mrow + 8][kk + tg + 4], ah[3], al[3]);
#pragma unroll
            for (int j = 0; j < 4; j++) {
                int nrow = wn * 32 + j * 8 + gid;
                unsigned bh[2], bl[2];
                split2(Bs[nrow][kk + tg],     bh[0], bl[0]);
                split2(Bs[nrow][kk + tg + 4], bh[1], bl[1]);
                mma8(acc[j], al, bh); mma8(acc[j], ah, bl); mma8(acc[j], ah, bh);
            }
        }
        __syncthreads();
    }

    // epilogue: per-row token/slot lookup, store to y
    int mA = m0 + wm * 16 + gid;
    int mB = mA + 8;
    int tA = 0, sA = 0, tB = 0, sB = 0;
    if (mA < cnt) { tA = g_tok[e * T + mA]; sA = g_slot[e * T + mA]; }
    if (mB < cnt) { tB = g_tok[e * T + mB]; sB = g_slot[e * T + mB]; }
#pragma unroll
    for (int j = 0; j < 4; j++) {
        int col = h0 + wn * 32 + j * 8 + tg * 2;
        if (mA < cnt)
            *(float2*)(g_y + ((size_t)(tA * TK + sA)) * HD + col)
                = make_float2(acc[j][0], acc[j][1]);
        if (mB < cnt)
            *(float2*)(g_y + ((size_t)(tB * TK + sB)) * HD + col)
                = make_float2(acc[j][2], acc[j][3]);
    }
}

// ---------------- combine ----------------
__global__ void combine_kernel(float* __restrict__ out) {
    int idx = blockIdx.x * blockDim.x + threadIdx.x;
    int t = idx / (HD / 4);
    int h4 = (idx % (HD / 4)) * 4;
    float4 o = make_float4(0.f, 0.f, 0.f, 0.f);
#pragma unroll
    for (int k = 0; k < TK; k++) {
        float w = g_wt[t * TK + k];
        float4 yv = *(const float4*)(g_y + ((size_t)(t * TK + k)) * HD + h4);
        o.x += w * yv.x; o.y += w * yv.y; o.z += w * yv.z; o.w += w * yv.w;
    }
    *(float4*)(out + (size_t)t * HD + h4) = o;
}

// ---------------- launcher ----------------
extern "C" void kernel_launch(void* const* d_in, const int* in_sizes, int n_in,
                              void* d_out, int out_size) {
    const float* hidden = (const float*)d_in[0];
    const float* logits = (const float*)d_in[1];
    const float* bias   = (const float*)d_in[2];
    const float* w13    = (const float*)d_in[3];
    const float* w2     = (const float*)d_in[4];
    float* out = (float*)d_out;

    routing_kernel<<<1, 256>>>(logits, bias);

    dim3 g1(ID / 64, T / BM, NE);   // 12 x 4 x 32
    gemm1_kernel<<<g1, 256>>>(hidden, w13);

    dim3 g2(HD / 64, T / BM, NE);   // 16 x 4 x 32
    gemm2_kernel<<<g2, 256>>>(w2);

    combine_kernel<<<(T * HD / 4) / 256, 256>>>(out);
}